// round 7
// baseline (speedup 1.0000x reference)
#include <cuda_runtime.h>
#include <math.h>

#define H    2048
#define TPB  256
#define NWARP (TPB / 32)
#define L    3

// Inter-layer hidden state
__device__ __align__(16) float g_hbuf[2][H];
// Precomputed P[l-1][gate][j] = (Wh_l @ h0_l)[gate*H+j] + bi + bh, layers 1,2
__device__ __align__(16) float g_P[2][4][H];

__device__ __forceinline__ float dot4(float4 w, float4 v) {
    return w.x * v.x + w.y * v.y + w.z * v.z + w.w * v.w;
}
__device__ __forceinline__ float sigmoidf_(float v) {
    return 1.0f / (1.0f + __expf(-v));
}

// ---------------------------------------------------------------------------
// K1a: full layer-0 cell, one block per output j (proven R1 body).
// ---------------------------------------------------------------------------
__global__ void __launch_bounds__(TPB) lstm_layer0_kernel(
    const float* __restrict__ x,
    const float* __restrict__ W_ih,
    const float* __restrict__ W_hh,
    const float* __restrict__ b_ih,
    const float* __restrict__ b_hh,
    const float* __restrict__ h0,
    const float* __restrict__ c0)
{
    const int j    = blockIdx.x;
    const int t    = threadIdx.x;
    const int warp = t >> 5;
    const int lane = t & 31;

    const float4* __restrict__ x4 = (const float4*)x;
    const float4* __restrict__ h4 = (const float4*)h0;

    const float4* __restrict__ wi0 = (const float4*)(W_ih + (size_t)(0 * H + j) * H);
    const float4* __restrict__ wi1 = (const float4*)(W_ih + (size_t)(1 * H + j) * H);
    const float4* __restrict__ wi2 = (const float4*)(W_ih + (size_t)(2 * H + j) * H);
    const float4* __restrict__ wi3 = (const float4*)(W_ih + (size_t)(3 * H + j) * H);
    const float4* __restrict__ wh0 = (const float4*)(W_hh + (size_t)(0 * H + j) * H);
    const float4* __restrict__ wh1 = (const float4*)(W_hh + (size_t)(1 * H + j) * H);
    const float4* __restrict__ wh2 = (const float4*)(W_hh + (size_t)(2 * H + j) * H);
    const float4* __restrict__ wh3 = (const float4*)(W_hh + (size_t)(3 * H + j) * H);

    float a0 = 0.f, a1 = 0.f, a2 = 0.f, a3 = 0.f;
    #pragma unroll
    for (int k = t; k < H / 4; k += TPB) {
        float4 xv = x4[k];
        float4 hv = h4[k];
        a0 += dot4(wi0[k], xv);
        a1 += dot4(wi1[k], xv);
        a2 += dot4(wi2[k], xv);
        a3 += dot4(wi3[k], xv);
        a0 += dot4(wh0[k], hv);
        a1 += dot4(wh1[k], hv);
        a2 += dot4(wh2[k], hv);
        a3 += dot4(wh3[k], hv);
    }
    #pragma unroll
    for (int off = 16; off > 0; off >>= 1) {
        a0 += __shfl_xor_sync(0xffffffffu, a0, off);
        a1 += __shfl_xor_sync(0xffffffffu, a1, off);
        a2 += __shfl_xor_sync(0xffffffffu, a2, off);
        a3 += __shfl_xor_sync(0xffffffffu, a3, off);
    }
    __shared__ float s[4][NWARP];
    if (lane == 0) { s[0][warp] = a0; s[1][warp] = a1; s[2][warp] = a2; s[3][warp] = a3; }
    __syncthreads();
    if (t == 0) {
        float gi = 0.f, gf = 0.f, gg = 0.f, go = 0.f;
        #pragma unroll
        for (int w = 0; w < NWARP; w++) {
            gi += s[0][w]; gf += s[1][w]; gg += s[2][w]; go += s[3][w];
        }
        gi += b_ih[0 * H + j] + b_hh[0 * H + j];
        gf += b_ih[1 * H + j] + b_hh[1 * H + j];
        gg += b_ih[2 * H + j] + b_hh[2 * H + j];
        go += b_ih[3 * H + j] + b_hh[3 * H + j];
        float iv = sigmoidf_(gi);
        float fv = sigmoidf_(gf);
        float gv = tanhf(gg);
        float ov = sigmoidf_(go);
        float c_new = fv * c0[j] + iv * gv;
        g_hbuf[0][j] = ov * tanhf(c_new);
    }
}

// ---------------------------------------------------------------------------
// KP: P precompute for one layer l: P[g][j] = (Wh_l @ h0_l)[g*H+j] + bi + bh.
// One block per j, 4 rows.
// ---------------------------------------------------------------------------
__global__ void __launch_bounds__(TPB, 8) lstm_prep_kernel(
    const float* __restrict__ Wh,    // [4H, H] layer l
    const float* __restrict__ bi,    // [4H]
    const float* __restrict__ bh,    // [4H]
    const float* __restrict__ hin,   // [H] = h0[l]
    float* __restrict__ P)           // [4][H]
{
    const int j    = blockIdx.x;
    const int t    = threadIdx.x;
    const int warp = t >> 5;
    const int lane = t & 31;

    const float4* __restrict__ h4 = (const float4*)hin;
    const float4* __restrict__ r0 = (const float4*)(Wh + (size_t)(0 * H + j) * H);
    const float4* __restrict__ r1 = (const float4*)(Wh + (size_t)(1 * H + j) * H);
    const float4* __restrict__ r2 = (const float4*)(Wh + (size_t)(2 * H + j) * H);
    const float4* __restrict__ r3 = (const float4*)(Wh + (size_t)(3 * H + j) * H);

    float a0 = 0.f, a1 = 0.f, a2 = 0.f, a3 = 0.f;
    #pragma unroll
    for (int k = t; k < H / 4; k += TPB) {
        float4 hv = h4[k];
        a0 += dot4(r0[k], hv);
        a1 += dot4(r1[k], hv);
        a2 += dot4(r2[k], hv);
        a3 += dot4(r3[k], hv);
    }
    #pragma unroll
    for (int off = 16; off > 0; off >>= 1) {
        a0 += __shfl_xor_sync(0xffffffffu, a0, off);
        a1 += __shfl_xor_sync(0xffffffffu, a1, off);
        a2 += __shfl_xor_sync(0xffffffffu, a2, off);
        a3 += __shfl_xor_sync(0xffffffffu, a3, off);
    }
    __shared__ float s[4][NWARP];
    if (lane == 0) { s[0][warp] = a0; s[1][warp] = a1; s[2][warp] = a2; s[3][warp] = a3; }
    __syncthreads();
    if (t == 0) {
        float p0 = 0.f, p1 = 0.f, p2 = 0.f, p3 = 0.f;
        #pragma unroll
        for (int w = 0; w < NWARP; w++) {
            p0 += s[0][w]; p1 += s[1][w]; p2 += s[2][w]; p3 += s[3][w];
        }
        P[0 * H + j] = p0 + bi[0 * H + j] + bh[0 * H + j];
        P[1 * H + j] = p1 + bi[1 * H + j] + bh[1 * H + j];
        P[2 * H + j] = p2 + bi[2 * H + j] + bh[2 * H + j];
        P[3 * H + j] = p3 + bi[3 * H + j] + bh[3 * H + j];
    }
}

// ---------------------------------------------------------------------------
// K2/K3: Wi_l @ x_l + P_l, epilogue. One block per j, 4 rows.
// ---------------------------------------------------------------------------
__global__ void __launch_bounds__(TPB, 8) lstm_wi_kernel(
    const float* __restrict__ Wi,    // [4H, H] layer l
    const float* __restrict__ xin,   // [H] = h of previous layer
    const float* __restrict__ cin,   // [H] = c0[l]
    const float* __restrict__ P,     // [4][H]
    float* __restrict__ hout)        // [H]
{
    const int j    = blockIdx.x;
    const int t    = threadIdx.x;
    const int warp = t >> 5;
    const int lane = t & 31;

    const float4* __restrict__ x4 = (const float4*)xin;
    const float4* __restrict__ r0 = (const float4*)(Wi + (size_t)(0 * H + j) * H);
    const float4* __restrict__ r1 = (const float4*)(Wi + (size_t)(1 * H + j) * H);
    const float4* __restrict__ r2 = (const float4*)(Wi + (size_t)(2 * H + j) * H);
    const float4* __restrict__ r3 = (const float4*)(Wi + (size_t)(3 * H + j) * H);

    float a0 = 0.f, a1 = 0.f, a2 = 0.f, a3 = 0.f;
    #pragma unroll
    for (int k = t; k < H / 4; k += TPB) {
        float4 xv = x4[k];
        a0 += dot4(r0[k], xv);
        a1 += dot4(r1[k], xv);
        a2 += dot4(r2[k], xv);
        a3 += dot4(r3[k], xv);
    }
    #pragma unroll
    for (int off = 16; off > 0; off >>= 1) {
        a0 += __shfl_xor_sync(0xffffffffu, a0, off);
        a1 += __shfl_xor_sync(0xffffffffu, a1, off);
        a2 += __shfl_xor_sync(0xffffffffu, a2, off);
        a3 += __shfl_xor_sync(0xffffffffu, a3, off);
    }
    __shared__ float s[4][NWARP];
    if (lane == 0) { s[0][warp] = a0; s[1][warp] = a1; s[2][warp] = a2; s[3][warp] = a3; }
    __syncthreads();
    if (t == 0) {
        float gi = 0.f, gf = 0.f, gg = 0.f, go = 0.f;
        #pragma unroll
        for (int w = 0; w < NWARP; w++) {
            gi += s[0][w]; gf += s[1][w]; gg += s[2][w]; go += s[3][w];
        }
        gi += P[0 * H + j];
        gf += P[1 * H + j];
        gg += P[2 * H + j];
        go += P[3 * H + j];
        float iv = sigmoidf_(gi);
        float fv = sigmoidf_(gf);
        float gv = tanhf(gg);
        float ov = sigmoidf_(go);
        float c_new = fv * cin[j] + iv * gv;
        hout[j] = ov * tanhf(c_new);
    }
}

extern "C" void kernel_launch(void* const* d_in, const int* in_sizes, int n_in,
                              void* d_out, int out_size) {
    (void)in_sizes; (void)n_in; (void)out_size;
    const float* x    = (const float*)d_in[0];
    const float* W_ih = (const float*)d_in[1];
    const float* W_hh = (const float*)d_in[2];
    const float* b_ih = (const float*)d_in[3];
    const float* b_hh = (const float*)d_in[4];
    const float* h0   = (const float*)d_in[5];
    const float* c0   = (const float*)d_in[6];
    float* out = (float*)d_out;

    float* hbuf;
    cudaGetSymbolAddress((void**)&hbuf, g_hbuf);
    float* P;
    cudaGetSymbolAddress((void**)&P, g_P);

    const size_t Wstride = (size_t)4 * H * H;
    const size_t bstride = (size_t)4 * H;

    // Side stream + events: created once on the first (non-captured)
    // correctness call; only launches/event ops happen during capture.
    static cudaStream_t s1 = nullptr;
    static cudaEvent_t eFork = nullptr, eP1 = nullptr, eP2 = nullptr;
    if (s1 == nullptr) {
        cudaStreamCreateWithFlags(&s1, cudaStreamNonBlocking);
        cudaEventCreateWithFlags(&eFork, cudaEventDisableTiming);
        cudaEventCreateWithFlags(&eP1,   cudaEventDisableTiming);
        cudaEventCreateWithFlags(&eP2,   cudaEventDisableTiming);
    }
    cudaStream_t s0 = 0;  // harness capture stream (legacy default)

    // Fork s1 from s0 so the side chain is part of the captured graph.
    cudaEventRecord(eFork, s0);

    // s0: layer-0 full cell (134 MB) — dispatched first, gets SMs first.
    lstm_layer0_kernel<<<H, TPB, 0, s0>>>(x, W_ih, W_hh, b_ih, b_hh, h0, c0);

    // s1: P precomputes (67 MB each). KP1 backfills K1a's tail; KP2 overlaps K2.
    cudaStreamWaitEvent(s1, eFork, 0);
    lstm_prep_kernel<<<H, TPB, 0, s1>>>(W_hh + Wstride,
                                        b_ih + bstride, b_hh + bstride,
                                        h0 + H, P);
    cudaEventRecord(eP1, s1);
    lstm_prep_kernel<<<H, TPB, 0, s1>>>(W_hh + 2 * Wstride,
                                        b_ih + 2 * bstride, b_hh + 2 * bstride,
                                        h0 + 2 * H, P + 4 * H);
    cudaEventRecord(eP2, s1);

    // s0: K2 needs {layer0 done (program order), P1}.
    cudaStreamWaitEvent(s0, eP1, 0);
    lstm_wi_kernel<<<H, TPB, 0, s0>>>(W_ih + Wstride, hbuf, c0 + H,
                                      P, hbuf + H);

    // s0: K3 needs {K2 (program order), P2} — also joins s1 back into s0.
    cudaStreamWaitEvent(s0, eP2, 0);
    lstm_wi_kernel<<<H, TPB, 0, s0>>>(W_ih + 2 * Wstride, hbuf + H, c0 + 2 * H,
                                      P + 4 * H, out);
}

// round 8
// speedup vs baseline: 1.0004x; 1.0004x over previous
#include <cuda_runtime.h>
#include <math.h>

#define H    2048
#define TPB  256
#define NWARP (TPB / 32)
#define L    3

// Dependent-phase kernel geometry: one block per j, all 2048 co-resident.
#define DTPB  128
#define DNWARP (DTPB / 32)

// Inter-layer hidden state: [0] = h1 (layer0 out), [1] = h2 (layer1 out)
__device__ __align__(16) float g_hbuf[2][H];
// Precomputed P[l-1][gate][j] = (Wh_l @ h0_l)[gate*H+j] + bi + bh, layers 1,2
__device__ __align__(16) float g_P[2][4][H];

// Grid barrier for the fused dependent kernel. count self-resets; sense
// alternates across replays (logic uses relative flip only) -> replay-safe.
__device__ unsigned g_bar_count = 0;
__device__ volatile unsigned g_bar_sense = 0;

__device__ __forceinline__ float dot4(float4 w, float4 v) {
    return w.x * v.x + w.y * v.y + w.z * v.z + w.w * v.w;
}
__device__ __forceinline__ float sigmoidf_(float v) {
    return 1.0f / (1.0f + __expf(-v));
}

// ---------------------------------------------------------------------------
// K1 (verbatim R5, measured 44.06us @ 78% DRAM): grid = 6144.
//   blocks [0,2048):     full layer-0 cell -> g_hbuf[0]
//   blocks [2048,4096):  P for layer 1     -> g_P[0]
//   blocks [4096,6144):  P for layer 2     -> g_P[1]
// ---------------------------------------------------------------------------
__global__ void __launch_bounds__(TPB) lstm_k1(
    const float* __restrict__ x,
    const float* __restrict__ W_ih,
    const float* __restrict__ W_hh,
    const float* __restrict__ b_ih,
    const float* __restrict__ b_hh,
    const float* __restrict__ h0,
    const float* __restrict__ c0)
{
    const int b    = blockIdx.x;
    const int t    = threadIdx.x;
    const int warp = t >> 5;
    const int lane = t & 31;

    __shared__ float s[4][NWARP];

    if (b < H) {
        const int j = b;
        const float4* __restrict__ x4 = (const float4*)x;
        const float4* __restrict__ h4 = (const float4*)h0;

        const float4* __restrict__ wi0 = (const float4*)(W_ih + (size_t)(0 * H + j) * H);
        const float4* __restrict__ wi1 = (const float4*)(W_ih + (size_t)(1 * H + j) * H);
        const float4* __restrict__ wi2 = (const float4*)(W_ih + (size_t)(2 * H + j) * H);
        const float4* __restrict__ wi3 = (const float4*)(W_ih + (size_t)(3 * H + j) * H);
        const float4* __restrict__ wh0 = (const float4*)(W_hh + (size_t)(0 * H + j) * H);
        const float4* __restrict__ wh1 = (const float4*)(W_hh + (size_t)(1 * H + j) * H);
        const float4* __restrict__ wh2 = (const float4*)(W_hh + (size_t)(2 * H + j) * H);
        const float4* __restrict__ wh3 = (const float4*)(W_hh + (size_t)(3 * H + j) * H);

        float a0 = 0.f, a1 = 0.f, a2 = 0.f, a3 = 0.f;
        #pragma unroll
        for (int k = t; k < H / 4; k += TPB) {
            float4 xv = x4[k];
            float4 hv = h4[k];
            a0 += dot4(wi0[k], xv);
            a1 += dot4(wi1[k], xv);
            a2 += dot4(wi2[k], xv);
            a3 += dot4(wi3[k], xv);
            a0 += dot4(wh0[k], hv);
            a1 += dot4(wh1[k], hv);
            a2 += dot4(wh2[k], hv);
            a3 += dot4(wh3[k], hv);
        }
        #pragma unroll
        for (int off = 16; off > 0; off >>= 1) {
            a0 += __shfl_xor_sync(0xffffffffu, a0, off);
            a1 += __shfl_xor_sync(0xffffffffu, a1, off);
            a2 += __shfl_xor_sync(0xffffffffu, a2, off);
            a3 += __shfl_xor_sync(0xffffffffu, a3, off);
        }
        if (lane == 0) { s[0][warp] = a0; s[1][warp] = a1; s[2][warp] = a2; s[3][warp] = a3; }
        __syncthreads();
        if (t == 0) {
            float gi = 0.f, gf = 0.f, gg = 0.f, go = 0.f;
            #pragma unroll
            for (int w = 0; w < NWARP; w++) {
                gi += s[0][w]; gf += s[1][w]; gg += s[2][w]; go += s[3][w];
            }
            gi += b_ih[0 * H + j] + b_hh[0 * H + j];
            gf += b_ih[1 * H + j] + b_hh[1 * H + j];
            gg += b_ih[2 * H + j] + b_hh[2 * H + j];
            go += b_ih[3 * H + j] + b_hh[3 * H + j];
            float iv = sigmoidf_(gi);
            float fv = sigmoidf_(gf);
            float gv = tanhf(gg);
            float ov = sigmoidf_(go);
            float c_new = fv * c0[j] + iv * gv;
            g_hbuf[0][j] = ov * tanhf(c_new);
        }
    } else {
        const int bb = b - H;
        const int l  = 1 + (bb >> 11);
        const int j  = bb & (H - 1);
        const float* Wh = W_hh + (size_t)l * 4 * H * H;
        const float* bi = b_ih + l * 4 * H;
        const float* bh = b_hh + l * 4 * H;
        const float4* __restrict__ h4 = (const float4*)(h0 + l * H);

        const float4* __restrict__ r0 = (const float4*)(Wh + (size_t)(0 * H + j) * H);
        const float4* __restrict__ r1 = (const float4*)(Wh + (size_t)(1 * H + j) * H);
        const float4* __restrict__ r2 = (const float4*)(Wh + (size_t)(2 * H + j) * H);
        const float4* __restrict__ r3 = (const float4*)(Wh + (size_t)(3 * H + j) * H);

        float a0 = 0.f, a1 = 0.f, a2 = 0.f, a3 = 0.f;
        #pragma unroll
        for (int k = t; k < H / 4; k += TPB) {
            float4 hv = h4[k];
            a0 += dot4(r0[k], hv);
            a1 += dot4(r1[k], hv);
            a2 += dot4(r2[k], hv);
            a3 += dot4(r3[k], hv);
        }
        #pragma unroll
        for (int off = 16; off > 0; off >>= 1) {
            a0 += __shfl_xor_sync(0xffffffffu, a0, off);
            a1 += __shfl_xor_sync(0xffffffffu, a1, off);
            a2 += __shfl_xor_sync(0xffffffffu, a2, off);
            a3 += __shfl_xor_sync(0xffffffffu, a3, off);
        }
        if (lane == 0) { s[0][warp] = a0; s[1][warp] = a1; s[2][warp] = a2; s[3][warp] = a3; }
        __syncthreads();
        if (t == 0) {
            float p0 = 0.f, p1 = 0.f, p2 = 0.f, p3 = 0.f;
            #pragma unroll
            for (int w = 0; w < NWARP; w++) {
                p0 += s[0][w]; p1 += s[1][w]; p2 += s[2][w]; p3 += s[3][w];
            }
            g_P[l - 1][0][j] = p0 + bi[0 * H + j] + bh[0 * H + j];
            g_P[l - 1][1][j] = p1 + bi[1 * H + j] + bh[1 * H + j];
            g_P[l - 1][2][j] = p2 + bi[2 * H + j] + bh[2 * H + j];
            g_P[l - 1][3][j] = p3 + bi[3 * H + j] + bh[3 * H + j];
        }
    }
}

// ---------------------------------------------------------------------------
// Fused dependent phase: layers 1 and 2 in one kernel with a grid barrier.
// grid = 2048 (one block per j), TPB = 128, forced 16 blocks/SM so ALL
// blocks are co-resident (2368 slots >= 2048): zero wave tail and a legal
// software grid barrier.
// ---------------------------------------------------------------------------
__device__ __forceinline__ void wi_half(
    const float* __restrict__ Wi, const float4* __restrict__ x4,
    const float* __restrict__ cin, const float* __restrict__ P,
    float* __restrict__ hout, int j, int t, int warp, int lane,
    float s[4][DNWARP])
{
    const float4* __restrict__ r0 = (const float4*)(Wi + (size_t)(0 * H + j) * H);
    const float4* __restrict__ r1 = (const float4*)(Wi + (size_t)(1 * H + j) * H);
    const float4* __restrict__ r2 = (const float4*)(Wi + (size_t)(2 * H + j) * H);
    const float4* __restrict__ r3 = (const float4*)(Wi + (size_t)(3 * H + j) * H);

    float a0 = 0.f, a1 = 0.f, a2 = 0.f, a3 = 0.f;
    #pragma unroll
    for (int k = t; k < H / 4; k += DTPB) {
        float4 xv = x4[k];
        a0 += dot4(r0[k], xv);
        a1 += dot4(r1[k], xv);
        a2 += dot4(r2[k], xv);
        a3 += dot4(r3[k], xv);
    }
    #pragma unroll
    for (int off = 16; off > 0; off >>= 1) {
        a0 += __shfl_xor_sync(0xffffffffu, a0, off);
        a1 += __shfl_xor_sync(0xffffffffu, a1, off);
        a2 += __shfl_xor_sync(0xffffffffu, a2, off);
        a3 += __shfl_xor_sync(0xffffffffu, a3, off);
    }
    if (lane == 0) { s[0][warp] = a0; s[1][warp] = a1; s[2][warp] = a2; s[3][warp] = a3; }
    __syncthreads();
    if (t == 0) {
        float gi = 0.f, gf = 0.f, gg = 0.f, go = 0.f;
        #pragma unroll
        for (int w = 0; w < DNWARP; w++) {
            gi += s[0][w]; gf += s[1][w]; gg += s[2][w]; go += s[3][w];
        }
        gi += P[0 * H + j];
        gf += P[1 * H + j];
        gg += P[2 * H + j];
        go += P[3 * H + j];
        float iv = sigmoidf_(gi);
        float fv = sigmoidf_(gf);
        float gv = tanhf(gg);
        float ov = sigmoidf_(go);
        float c_new = fv * cin[j] + iv * gv;
        hout[j] = ov * tanhf(c_new);
    }
    __syncthreads();  // s[][] reuse safety
}

__global__ void __launch_bounds__(DTPB, 16) lstm_dep_fused(
    const float* __restrict__ W_ih,  // [L, 4H, H]
    const float* __restrict__ c0,    // [L, H]
    float* __restrict__ out)         // [H]
{
    const int j    = blockIdx.x;
    const int t    = threadIdx.x;
    const int warp = t >> 5;
    const int lane = t & 31;

    __shared__ float s[4][DNWARP];

    // Read barrier sense BEFORE any work: every block reads its s0 before any
    // block can possibly flip (flip requires all arrivals, arrivals follow reads).
    const unsigned sense0 = g_bar_sense;

    // ---- Layer 1: h2[j] = cell(Wi_1 @ h1 + P_1) ----
    wi_half(W_ih + (size_t)4 * H * H, (const float4*)g_hbuf[0],
            c0 + H, &g_P[0][0][0], g_hbuf[1], j, t, warp, lane, s);

    // ---- Grid barrier ----
    if (t == 0) {
        __threadfence();
        unsigned prev = atomicAdd(&g_bar_count, 1u);
        if (prev == (unsigned)(gridDim.x - 1)) {
            g_bar_count = 0;              // self-reset for next replay
            __threadfence();
            g_bar_sense = sense0 ^ 1u;    // release
        } else {
            while (g_bar_sense == sense0) { __nanosleep(32); }
            __threadfence();
        }
    }
    __syncthreads();

    // ---- Layer 2: out[j] = cell(Wi_2 @ h2 + P_2) ----
    wi_half(W_ih + (size_t)8 * H * H, (const float4*)g_hbuf[1],
            c0 + 2 * H, &g_P[1][0][0], out, j, t, warp, lane, s);
}

extern "C" void kernel_launch(void* const* d_in, const int* in_sizes, int n_in,
                              void* d_out, int out_size) {
    (void)in_sizes; (void)n_in; (void)out_size;
    const float* x    = (const float*)d_in[0];
    const float* W_ih = (const float*)d_in[1];
    const float* W_hh = (const float*)d_in[2];
    const float* b_ih = (const float*)d_in[3];
    const float* b_hh = (const float*)d_in[4];
    const float* h0   = (const float*)d_in[5];
    const float* c0   = (const float*)d_in[6];
    float* out = (float*)d_out;

    // K1: all input-parallel work (268 MB, 6.92 near-full waves)
    lstm_k1<<<3 * H, TPB>>>(x, W_ih, W_hh, b_ih, b_hh, h0, c0);
    // K2: fused dependent phase (134 MB, single fully-resident wave + grid sync)
    lstm_dep_fused<<<H, DTPB>>>(W_ih, c0, out);
}